// round 3
// baseline (speedup 1.0000x reference)
#include <cuda_runtime.h>
#include <cstdint>

// Problem constants
#define B_       512
#define P_       65536
#define NOUT_    512
#define COUT_    4
#define NCLS_    10

// Tiling
#define SLICES   32
#define SLICE_P  (P_ / SLICES)       // 2048
#define TILE_P   128
#define NTILES   (SLICE_P / TILE_P)  // 16
#define ROWS_    32
#define RGROUPS  (B_ / ROWS_)        // 16
#define XSTRIDE  132                 // smem row stride in floats (528B, 16B-aligned, conflict-free LDS.128)

// Scratch (allocation-free: __device__ globals)
__device__ float  g_Weff[NOUT_ * NCLS_];
__device__ float  g_beff[NCLS_];
__device__ float4 g_wp2[(P_ / 2) * 5];            // packed pair-weights, 2.62 MB
__device__ float  g_partial[SLICES * B_ * NCLS_]; // per-slice partial sums

__device__ __forceinline__ uint32_t smem_u32(const void* p) {
    return (uint32_t)__cvta_generic_to_shared(p);
}

__device__ __forceinline__ void cp16(void* smem, const void* gmem) {
    uint32_t a = smem_u32(smem);
    asm volatile("cp.async.cg.shared.global [%0], [%1], 16;" :: "r"(a), "l"(gmem));
}

// ---------------------------------------------------------------------------
// Prep 1: Weff[j,k] = sum_c W_fgl[c,j] * W_fc[c*NOUT+j, k]
//         beff[k]   = b_fc[k] + sum_{c,j} b_fgl[c,j] * W_fc[c*NOUT+j, k]
// grid 17 x 320: blocks 0..15 compute Weff (32 j each), block 16 computes beff.
// ---------------------------------------------------------------------------
__global__ void prep_weff_k(const float* __restrict__ W_fgl,
                            const float* __restrict__ b_fgl,
                            const float* __restrict__ W_fc,
                            const float* __restrict__ b_fc) {
    if (blockIdx.x < 16) {
        int t = threadIdx.x;                  // 0..319
        int j = blockIdx.x * 32 + t / NCLS_;
        int k = t % NCLS_;
        float s = 0.f;
#pragma unroll
        for (int c = 0; c < COUT_; c++) {
            int r = c * NOUT_ + j;
            s += W_fgl[r] * W_fc[r * NCLS_ + k];
        }
        g_Weff[j * NCLS_ + k] = s;
    } else {
        __shared__ float red[256][NCLS_];
        int t = threadIdx.x;
        if (t < 256) {
            float loc[NCLS_];
#pragma unroll
            for (int k = 0; k < NCLS_; k++) loc[k] = 0.f;
            for (int r = t; r < COUT_ * NOUT_; r += 256) {
                float bb = b_fgl[r];
#pragma unroll
                for (int k = 0; k < NCLS_; k++) loc[k] += bb * W_fc[r * NCLS_ + k];
            }
#pragma unroll
            for (int k = 0; k < NCLS_; k++) red[t][k] = loc[k];
        }
        __syncthreads();
        if (t < NCLS_) {
            float s = b_fc[t];
            for (int i = 0; i < 256; i++) s += red[i][t];  // fixed order: deterministic
            g_beff[t] = s;
        }
    }
}

// ---------------------------------------------------------------------------
// Prep 2: gather + pack weights for the f32x2 inner loop.
// For pixel pair pp (p = 2pp, 2pp+1) and class pair q (k = 2q, 2q+1):
//   g_wp2[pp*5+q] = ( W[2pp][2q], W[2pp+1][2q], W[2pp][2q+1], W[2pp+1][2q+1] )
// where W[p][k] = Weff[seg[p]][k].
// ---------------------------------------------------------------------------
__global__ void prep_wp2_k(const int* __restrict__ seg) {
    int pp = blockIdx.x * blockDim.x + threadIdx.x;
    if (pp >= P_ / 2) return;
    int s0 = seg[2 * pp];
    int s1 = seg[2 * pp + 1];
    const float* w0 = g_Weff + s0 * NCLS_;
    const float* w1 = g_Weff + s1 * NCLS_;
#pragma unroll
    for (int q = 0; q < 5; q++) {
        g_wp2[(size_t)pp * 5 + q] =
            make_float4(w0[2 * q], w1[2 * q], w0[2 * q + 1], w1[2 * q + 1]);
    }
}

// ---------------------------------------------------------------------------
// Main: C_partial[s, n, k] = sum_{p in slice s} x[n,p] * W[p][k]
// Block (s, g): 32 rows (lane == row), 2048-p slice, 16 double-buffered tiles.
// Warp w handles i in [w*16, w*16+16) of each 128-p tile, all 32 rows.
// Inner loop: ld.shared.v2.b64 (x and broadcast w) + fma.rn.f32x2.
// ---------------------------------------------------------------------------
__global__ void __launch_bounds__(256, 4)
fused_main_k(const float* __restrict__ x) {
    __shared__ __align__(16) float  xs[2][ROWS_ * XSTRIDE];       // 33.8 KB
    __shared__ __align__(16) float4 ws[2][(TILE_P / 2) * 5];      // 10.25 KB

    const int t    = threadIdx.x;
    const int warp = t >> 5;
    const int lane = t & 31;
    const int s    = blockIdx.x;
    const int g    = blockIdx.y;

    const float*  xbase = x + (size_t)(g * ROWS_) * P_ + (size_t)s * SLICE_P;
    const float4* wbase = g_wp2 + (size_t)s * (SLICE_P / 2) * 5;

    unsigned long long acc[NCLS_];   // f32x2 accumulators: lo=even-p terms, hi=odd-p
#pragma unroll
    for (int k = 0; k < NCLS_; k++) acc[k] = 0ull;

    auto stage = [&](int tile, int buf) {
        const int pOff = tile * TILE_P;
        // x tile: 32 rows x 128 floats = 1024 float4 (coalesced, 4 per thread)
#pragma unroll
        for (int r = 0; r < 4; r++) {
            int f   = r * 256 + t;
            int row = f >> 5;          // 32 float4 per row
            int c4  = (f & 31) << 2;
            cp16(&xs[buf][row * XSTRIDE + c4], xbase + (size_t)row * P_ + pOff + c4);
        }
        // w tile: 64 pairs x 5 float4 = 320 float4
        const float4* wsrc = wbase + (size_t)(tile * (TILE_P / 2)) * 5;
        cp16(&ws[buf][t], wsrc + t);
        if (t < (TILE_P / 2) * 5 - 256)
            cp16(&ws[buf][256 + t], wsrc + 256 + t);
    };

    auto compute = [&](int buf) {
        uint32_t xa = smem_u32(&xs[buf][lane * XSTRIDE + warp * 16]);
        uint32_t wa = smem_u32(&ws[buf][(warp * 8) * 5]);
#pragma unroll
        for (int step = 0; step < 4; step++) {
            unsigned long long x01, x23;   // (x[i],x[i+1]), (x[i+2],x[i+3])
            asm volatile("ld.shared.v2.b64 {%0,%1}, [%2];"
                         : "=l"(x01), "=l"(x23)
                         : "r"(xa + step * 16));
#pragma unroll
            for (int half = 0; half < 2; half++) {
                unsigned long long xh = half ? x23 : x01;
                uint32_t wpa = wa + ((step * 2 + half) * 5) * 16;
#pragma unroll
                for (int q = 0; q < 5; q++) {
                    unsigned long long wA, wB;  // broadcast across warp
                    asm volatile("ld.shared.v2.b64 {%0,%1}, [%2];"
                                 : "=l"(wA), "=l"(wB)
                                 : "r"(wpa + q * 16));
                    asm("fma.rn.f32x2 %0, %1, %2, %0;"
                        : "+l"(acc[2 * q])     : "l"(xh), "l"(wA));
                    asm("fma.rn.f32x2 %0, %1, %2, %0;"
                        : "+l"(acc[2 * q + 1]) : "l"(xh), "l"(wB));
                }
            }
        }
    };

    stage(0, 0);
    asm volatile("cp.async.commit_group;");
#pragma unroll 1
    for (int tile = 0; tile < NTILES; tile++) {
        int buf = tile & 1;
        if (tile + 1 < NTILES) {
            stage(tile + 1, buf ^ 1);
            asm volatile("cp.async.commit_group;");
            asm volatile("cp.async.wait_group 1;");
        } else {
            asm volatile("cp.async.wait_group 0;");
        }
        __syncthreads();
        compute(buf);
        __syncthreads();   // protects buf before it is restaged at tile+2
    }

    // Cross-warp reduction (deterministic, fixed order), then write partials.
    float* red = &xs[0][0];   // reuse x smem: 256*10 floats
#pragma unroll
    for (int k = 0; k < NCLS_; k++) {
        float lo, hi;
        asm("mov.b64 {%0,%1}, %2;" : "=f"(lo), "=f"(hi) : "l"(acc[k]));
        red[t * NCLS_ + k] = lo + hi;
    }
    __syncthreads();
    // ROWS_*NCLS_ = 320 > blockDim (256): strided loop (R1 fix — the old
    // `if (t < 320)` guard left rows 25..31 of every group unwritten).
    for (int i = t; i < ROWS_ * NCLS_; i += 256) {
        int row = i / NCLS_;
        int k   = i - row * NCLS_;
        float sum = 0.f;
#pragma unroll
        for (int w = 0; w < 8; w++) sum += red[(w * 32 + row) * NCLS_ + k];
        g_partial[((size_t)s * B_ + g * ROWS_ + row) * NCLS_ + k] = sum;
    }
}

// ---------------------------------------------------------------------------
// Finalize: out[n,k] = beff[k] + sum_s partial[s,n,k]   (coalesced per s-plane)
// ---------------------------------------------------------------------------
__global__ void finalize_k(float* __restrict__ out) {
    int t = blockIdx.x * blockDim.x + threadIdx.x;
    if (t >= B_ * NCLS_) return;
    int k = t % NCLS_;
    float sum = g_beff[k];
#pragma unroll 1
    for (int s = 0; s < SLICES; s++) sum += g_partial[s * (B_ * NCLS_) + t];
    out[t] = sum;
}

// ---------------------------------------------------------------------------
extern "C" void kernel_launch(void* const* d_in, const int* in_sizes, int n_in,
                              void* d_out, int out_size) {
    const float* x     = (const float*)d_in[0];   // [512, 65536]
    const float* W_fgl = (const float*)d_in[1];   // [4, 512]
    const float* b_fgl = (const float*)d_in[2];   // [4, 512]
    const float* W_fc  = (const float*)d_in[3];   // [2048, 10]
    const float* b_fc  = (const float*)d_in[4];   // [10]
    const int*   seg   = (const int*)d_in[5];     // [65536]
    float* out = (float*)d_out;                   // [512, 10]

    prep_weff_k<<<17, 320>>>(W_fgl, b_fgl, W_fc, b_fc);
    prep_wp2_k<<<(P_ / 2 + 255) / 256, 256>>>(seg);
    fused_main_k<<<dim3(SLICES, RGROUPS), 256>>>(x);
    finalize_k<<<(B_ * NCLS_ + 255) / 256, 256>>>(out);
    (void)in_sizes; (void)n_in; (void)out_size;
}

// round 4
// speedup vs baseline: 1.1535x; 1.1535x over previous
#include <cuda_runtime.h>
#include <cstdint>

// Problem constants
#define B_       512
#define P_       65536
#define NOUT_    512
#define COUT_    4
#define NCLS_    10

// Tiling
#define SLICES   32
#define SLICE_P  (P_ / SLICES)       // 2048
#define TILE_P   128
#define NTILES   (SLICE_P / TILE_P)  // 16
#define ROWS_    32
#define RGROUPS  (B_ / ROWS_)        // 16
#define XSTRIDE  132                 // smem row stride in floats (528B, 16B-aligned, conflict-free LDS.128)

// Scratch (allocation-free: __device__ globals)
__device__ float  g_Weff[NOUT_ * NCLS_];
__device__ float  g_beff[NCLS_];
__device__ float4 g_wp2[(P_ / 2) * 5];            // packed pair-weights, 2.62 MB
__device__ float  g_partial[SLICES * B_ * NCLS_]; // per-slice partial sums

__device__ __forceinline__ uint32_t smem_u32(const void* p) {
    return (uint32_t)__cvta_generic_to_shared(p);
}

__device__ __forceinline__ void cp16(void* smem, const void* gmem) {
    uint32_t a = smem_u32(smem);
    asm volatile("cp.async.cg.shared.global [%0], [%1], 16;" :: "r"(a), "l"(gmem));
}

// ---------------------------------------------------------------------------
// Prep 1: Weff[j,k] = sum_c W_fgl[c,j] * W_fc[c*NOUT+j, k]
//         beff[k]   = b_fc[k] + sum_{c,j} b_fgl[c,j] * W_fc[c*NOUT+j, k]
// grid 17 x 320: blocks 0..15 compute Weff (32 j each), block 16 computes beff.
// ---------------------------------------------------------------------------
__global__ void prep_weff_k(const float* __restrict__ W_fgl,
                            const float* __restrict__ b_fgl,
                            const float* __restrict__ W_fc,
                            const float* __restrict__ b_fc) {
    if (blockIdx.x < 16) {
        int t = threadIdx.x;                  // 0..319
        int j = blockIdx.x * 32 + t / NCLS_;
        int k = t % NCLS_;
        float s = 0.f;
#pragma unroll
        for (int c = 0; c < COUT_; c++) {
            int r = c * NOUT_ + j;
            s += W_fgl[r] * W_fc[r * NCLS_ + k];
        }
        g_Weff[j * NCLS_ + k] = s;
    } else {
        __shared__ float red[256][NCLS_];
        int t = threadIdx.x;
        if (t < 256) {
            float loc[NCLS_];
#pragma unroll
            for (int k = 0; k < NCLS_; k++) loc[k] = 0.f;
            for (int r = t; r < COUT_ * NOUT_; r += 256) {
                float bb = b_fgl[r];
#pragma unroll
                for (int k = 0; k < NCLS_; k++) loc[k] += bb * W_fc[r * NCLS_ + k];
            }
#pragma unroll
            for (int k = 0; k < NCLS_; k++) red[t][k] = loc[k];
        }
        __syncthreads();
        if (t < NCLS_) {
            float s = b_fc[t];
            for (int i = 0; i < 256; i++) s += red[i][t];  // fixed order: deterministic
            g_beff[t] = s;
        }
    }
}

// ---------------------------------------------------------------------------
// Prep 2: gather + pack weights for the f32x2 inner loop.
// For pixel pair pp (p = 2pp, 2pp+1) and class pair q (k = 2q, 2q+1):
//   g_wp2[pp*5+q] = ( W[2pp][2q], W[2pp+1][2q], W[2pp][2q+1], W[2pp+1][2q+1] )
// where W[p][k] = Weff[seg[p]][k].
// ---------------------------------------------------------------------------
__global__ void prep_wp2_k(const int* __restrict__ seg) {
    int pp = blockIdx.x * blockDim.x + threadIdx.x;
    if (pp >= P_ / 2) return;
    int s0 = seg[2 * pp];
    int s1 = seg[2 * pp + 1];
    const float* w0 = g_Weff + s0 * NCLS_;
    const float* w1 = g_Weff + s1 * NCLS_;
#pragma unroll
    for (int q = 0; q < 5; q++) {
        g_wp2[(size_t)pp * 5 + q] =
            make_float4(w0[2 * q], w1[2 * q], w0[2 * q + 1], w1[2 * q + 1]);
    }
}

// ---------------------------------------------------------------------------
// Main: C_partial[s, n, k] = sum_{p in slice s} x[n,p] * W[p][k]
// Block (s, g): 32 rows (lane == row), 2048-p slice, 16 double-buffered tiles.
// Warp w handles i in [w*16, w*16+16) of each 128-p tile, all 32 rows.
// Inner loop: ld.shared.v2.b64 (x and broadcast w) + fma.rn.f32x2.
// ---------------------------------------------------------------------------
__global__ void __launch_bounds__(256, 4)
fused_main_k(const float* __restrict__ x) {
    __shared__ __align__(16) float  xs[2][ROWS_ * XSTRIDE];       // 33.8 KB
    __shared__ __align__(16) float4 ws[2][(TILE_P / 2) * 5];      // 10.25 KB

    const int t    = threadIdx.x;
    const int warp = t >> 5;
    const int lane = t & 31;
    const int s    = blockIdx.x;
    const int g    = blockIdx.y;

    const float*  xbase = x + (size_t)(g * ROWS_) * P_ + (size_t)s * SLICE_P;
    const float4* wbase = g_wp2 + (size_t)s * (SLICE_P / 2) * 5;

    unsigned long long acc[NCLS_];   // f32x2 accumulators: lo=even-p terms, hi=odd-p
#pragma unroll
    for (int k = 0; k < NCLS_; k++) acc[k] = 0ull;

    auto stage = [&](int tile, int buf) {
        const int pOff = tile * TILE_P;
        // x tile: 32 rows x 128 floats = 1024 float4 (coalesced, 4 per thread)
#pragma unroll
        for (int r = 0; r < 4; r++) {
            int f   = r * 256 + t;
            int row = f >> 5;          // 32 float4 per row
            int c4  = (f & 31) << 2;
            cp16(&xs[buf][row * XSTRIDE + c4], xbase + (size_t)row * P_ + pOff + c4);
        }
        // w tile: 64 pairs x 5 float4 = 320 float4
        const float4* wsrc = wbase + (size_t)(tile * (TILE_P / 2)) * 5;
        cp16(&ws[buf][t], wsrc + t);
        if (t < (TILE_P / 2) * 5 - 256)
            cp16(&ws[buf][256 + t], wsrc + 256 + t);
    };

    auto compute = [&](int buf) {
        uint32_t xa = smem_u32(&xs[buf][lane * XSTRIDE + warp * 16]);
        uint32_t wa = smem_u32(&ws[buf][(warp * 8) * 5]);
#pragma unroll
        for (int step = 0; step < 4; step++) {
            unsigned long long x01, x23;   // (x[i],x[i+1]), (x[i+2],x[i+3])
            asm volatile("ld.shared.v2.b64 {%0,%1}, [%2];"
                         : "=l"(x01), "=l"(x23)
                         : "r"(xa + step * 16));
#pragma unroll
            for (int half = 0; half < 2; half++) {
                unsigned long long xh = half ? x23 : x01;
                uint32_t wpa = wa + ((step * 2 + half) * 5) * 16;
#pragma unroll
                for (int q = 0; q < 5; q++) {
                    unsigned long long wA, wB;  // broadcast across warp
                    asm volatile("ld.shared.v2.b64 {%0,%1}, [%2];"
                                 : "=l"(wA), "=l"(wB)
                                 : "r"(wpa + q * 16));
                    asm("fma.rn.f32x2 %0, %1, %2, %0;"
                        : "+l"(acc[2 * q])     : "l"(xh), "l"(wA));
                    asm("fma.rn.f32x2 %0, %1, %2, %0;"
                        : "+l"(acc[2 * q + 1]) : "l"(xh), "l"(wB));
                }
            }
        }
    };

    stage(0, 0);
    asm volatile("cp.async.commit_group;");
#pragma unroll 1
    for (int tile = 0; tile < NTILES; tile++) {
        int buf = tile & 1;
        if (tile + 1 < NTILES) {
            stage(tile + 1, buf ^ 1);
            asm volatile("cp.async.commit_group;");
            asm volatile("cp.async.wait_group 1;");
        } else {
            asm volatile("cp.async.wait_group 0;");
        }
        __syncthreads();
        compute(buf);
        __syncthreads();   // protects buf before it is restaged at tile+2
    }

    // Cross-warp reduction (deterministic, fixed order), then write partials.
    float* red = &xs[0][0];   // reuse x smem: 256*10 floats
#pragma unroll
    for (int k = 0; k < NCLS_; k++) {
        float lo, hi;
        asm("mov.b64 {%0,%1}, %2;" : "=f"(lo), "=f"(hi) : "l"(acc[k]));
        red[t * NCLS_ + k] = lo + hi;
    }
    __syncthreads();
    // ROWS_*NCLS_ = 320 > blockDim (256): strided loop.
    for (int i = t; i < ROWS_ * NCLS_; i += 256) {
        int row = i / NCLS_;
        int k   = i - row * NCLS_;
        float sum = 0.f;
#pragma unroll
        for (int w = 0; w < 8; w++) sum += red[(w * 32 + row) * NCLS_ + k];
        g_partial[((size_t)s * B_ + g * ROWS_ + row) * NCLS_ + k] = sum;
    }
}

// ---------------------------------------------------------------------------
// Finalize: out[n,k] = beff[k] + sum_s partial[s,n,k]
// R3 fix: the slice loop was `#pragma unroll 1` -> MLP=1 -> 32 serialized DRAM
// latencies per thread (measured 18.9us, DRAM 0.4%, issue 1.7%). Fully unroll
// so all 32 LDGs are in flight at once (MLP=32 overlaps latency completely),
// and use 40 blocks x 128 threads to spread across SMs.
// ---------------------------------------------------------------------------
__global__ void __launch_bounds__(128)
finalize_k(float* __restrict__ out) {
    int t = blockIdx.x * blockDim.x + threadIdx.x;
    if (t >= B_ * NCLS_) return;
    int k = t % NCLS_;
    float v[SLICES];
#pragma unroll
    for (int s = 0; s < SLICES; s++) v[s] = g_partial[s * (B_ * NCLS_) + t];
    float sum = g_beff[k];
#pragma unroll
    for (int s = 0; s < SLICES; s++) sum += v[s];
    out[t] = sum;
}

// ---------------------------------------------------------------------------
extern "C" void kernel_launch(void* const* d_in, const int* in_sizes, int n_in,
                              void* d_out, int out_size) {
    const float* x     = (const float*)d_in[0];   // [512, 65536]
    const float* W_fgl = (const float*)d_in[1];   // [4, 512]
    const float* b_fgl = (const float*)d_in[2];   // [4, 512]
    const float* W_fc  = (const float*)d_in[3];   // [2048, 10]
    const float* b_fc  = (const float*)d_in[4];   // [10]
    const int*   seg   = (const int*)d_in[5];     // [65536]
    float* out = (float*)d_out;                   // [512, 10]

    prep_weff_k<<<17, 320>>>(W_fgl, b_fgl, W_fc, b_fc);
    prep_wp2_k<<<(P_ / 2 + 255) / 256, 256>>>(seg);
    fused_main_k<<<dim3(SLICES, RGROUPS), 256>>>(x);
    finalize_k<<<(B_ * NCLS_ + 127) / 128, 128>>>(out);
    (void)in_sizes; (void)n_in; (void)out_size;
}

// round 6
// speedup vs baseline: 1.1542x; 1.0006x over previous
#include <cuda_runtime.h>
#include <cstdint>

// Problem constants
#define B_       512
#define P_       65536
#define NOUT_    512
#define COUT_    4
#define NCLS_    10

// Tiling
#define SLICES   32
#define SLICE_P  (P_ / SLICES)       // 2048
#define TILE_P   128
#define NTILES   (SLICE_P / TILE_P)  // 16
#define ROWS_    32
#define RGROUPS  (B_ / ROWS_)        // 16
#define XSTRIDE  132                 // smem row stride in floats (528B, 16B-aligned, conflict-free LDS.128)
#define WPAD     12                  // Weff row padded to 12 floats (48B, 16B-aligned)

// Dynamic smem layout (bytes): [xs | wsm | segs], all 16B-multiples
#define XS_BYTES   (2 * ROWS_ * XSTRIDE * 4)     // 33792
#define WSM_BYTES  (NOUT_ * WPAD * 4)            // 24576
#define SEG_BYTES  (SLICE_P * 4)                 // 8192
#define SMEM_TOTAL (XS_BYTES + WSM_BYTES + SEG_BYTES)  // 66560 (> 48K static cap -> dynamic)

// Scratch (allocation-free: __device__ globals)
__device__ float g_Weff[NOUT_ * WPAD];            // padded [512][12]
__device__ float g_beff[NCLS_];
__device__ float g_partial[SLICES * B_ * NCLS_];  // per-slice partial sums

__device__ __forceinline__ uint32_t smem_u32(const void* p) {
    return (uint32_t)__cvta_generic_to_shared(p);
}
__device__ __forceinline__ void cp16(void* smem, const void* gmem) {
    uint32_t a = smem_u32(smem);
    asm volatile("cp.async.cg.shared.global [%0], [%1], 16;" :: "r"(a), "l"(gmem));
}
__device__ __forceinline__ unsigned long long packf2(float v) {
    unsigned long long r;
    asm("mov.b64 %0, {%1, %1};" : "=l"(r) : "f"(v));
    return r;
}

// ---------------------------------------------------------------------------
// Prep: Weff[j][k] = sum_c W_fgl[c,j] * W_fc[c*NOUT+j, k]   (padded rows)
//       beff[k]    = b_fc[k] + sum_{c,j} b_fgl[c,j] * W_fc[c*NOUT+j, k]
// grid 17 x 320: blocks 0..15 -> Weff (32 j each), block 16 -> beff.
// ---------------------------------------------------------------------------
__global__ void prep_k(const float* __restrict__ W_fgl,
                       const float* __restrict__ b_fgl,
                       const float* __restrict__ W_fc,
                       const float* __restrict__ b_fc) {
    if (blockIdx.x < 16) {
        int t = threadIdx.x;                  // 0..319
        int j = blockIdx.x * 32 + t / NCLS_;
        int k = t % NCLS_;
        float s = 0.f;
#pragma unroll
        for (int c = 0; c < COUT_; c++) {
            int r = c * NOUT_ + j;
            s += W_fgl[r] * W_fc[r * NCLS_ + k];
        }
        g_Weff[j * WPAD + k] = s;
        if (k < 2) g_Weff[j * WPAD + 10 + k] = 0.f;   // pad (never read, keep defined)
    } else {
        __shared__ float red[256][NCLS_];
        int t = threadIdx.x;
        if (t < 256) {
            float loc[NCLS_];
#pragma unroll
            for (int k = 0; k < NCLS_; k++) loc[k] = 0.f;
            for (int r = t; r < COUT_ * NOUT_; r += 256) {
                float bb = b_fgl[r];
#pragma unroll
                for (int k = 0; k < NCLS_; k++) loc[k] += bb * W_fc[r * NCLS_ + k];
            }
#pragma unroll
            for (int k = 0; k < NCLS_; k++) red[t][k] = loc[k];
        }
        __syncthreads();
        if (t < NCLS_) {
            float s = b_fc[t];
            for (int i = 0; i < 256; i++) s += red[i][t];  // fixed order: deterministic
            g_beff[t] = s;
        }
    }
}

// ---------------------------------------------------------------------------
// Main: partial[s, n, k] = sum_{p in slice s} x[n,p] * Weff[seg[p]][k]
// Block (s, g): 32 rows (lane == row), 2048-p slice, 16 double-buffered x tiles.
// Weff table (24 KB) + slice seg ids (8 KB) resident in DYNAMIC smem for the
// whole block; per-pixel weight lookup is a UNIFORM address per warp ->
// broadcast LDS, no per-pixel weight materialization in gmem.
// acc[q] packs class pair (2q, 2q+1); x value replicated into both f32x2 lanes.
// ---------------------------------------------------------------------------
__global__ void __launch_bounds__(256, 3)
fused_main_k(const float* __restrict__ x, const int* __restrict__ seg) {
    extern __shared__ __align__(16) char dynsmem[];
    float* xs0  = (float*)dynsmem;                         // [2][ROWS_*XSTRIDE]
    float* wsm  = (float*)(dynsmem + XS_BYTES);            // [NOUT_*WPAD]
    int*   segs = (int*)(dynsmem + XS_BYTES + WSM_BYTES);  // [SLICE_P]

    const int t    = threadIdx.x;
    const int warp = t >> 5;
    const int lane = t & 31;
    const int s    = blockIdx.x;
    const int g    = blockIdx.y;

    const float* xbase = x + (size_t)(g * ROWS_) * P_ + (size_t)s * SLICE_P;

    // Prologue staging (one cp.async group): Weff table, seg slice, x tile 0.
    {
        const float4* wsrc = (const float4*)g_Weff;          // 1536 float4
#pragma unroll
        for (int r = 0; r < 6; r++)
            cp16(&((float4*)wsm)[r * 256 + t], wsrc + r * 256 + t);
        const float4* ssrc = (const float4*)(seg + s * SLICE_P);  // 512 float4
#pragma unroll
        for (int r = 0; r < 2; r++)
            cp16(&((float4*)segs)[r * 256 + t], ssrc + r * 256 + t);
    }
    auto stage_x = [&](int tile, int buf) {
        const int pOff = tile * TILE_P;
        float* xsb = xs0 + buf * (ROWS_ * XSTRIDE);
#pragma unroll
        for (int r = 0; r < 4; r++) {
            int f   = r * 256 + t;
            int row = f >> 5;            // 32 float4 per row
            int c4  = (f & 31) << 2;
            cp16(&xsb[row * XSTRIDE + c4], xbase + (size_t)row * P_ + pOff + c4);
        }
    };
    stage_x(0, 0);
    asm volatile("cp.async.commit_group;");

    unsigned long long acc[5];   // f32x2 per class pair
#pragma unroll
    for (int q = 0; q < 5; q++) acc[q] = 0ull;

    auto compute = [&](int buf, int tile) {
        const float4* xrow =
            (const float4*)&xs0[buf * (ROWS_ * XSTRIDE) + lane * XSTRIDE + warp * 16];
        const int4* sp = (const int4*)&segs[tile * TILE_P + warp * 16];
#pragma unroll
        for (int step = 0; step < 4; step++) {
            float4 x4  = xrow[step];          // 4 pixels of this row (LDS.128)
            int4   sid = sp[step];            // 4 seg ids (uniform -> broadcast)
#pragma unroll
            for (int j = 0; j < 4; j++) {
                int   id = (j == 0) ? sid.x : (j == 1) ? sid.y : (j == 2) ? sid.z : sid.w;
                float xv = (j == 0) ? x4.x  : (j == 1) ? x4.y  : (j == 2) ? x4.z  : x4.w;
                const unsigned long long* wrow =
                    (const unsigned long long*)&wsm[id * WPAD];
                ulonglong2 wab = *(const ulonglong2*)(wrow);      // k0..3
                ulonglong2 wcd = *(const ulonglong2*)(wrow + 2);  // k4..7
                unsigned long long we = wrow[4];                   // k8..9
                unsigned long long xp = packf2(xv);
                asm("fma.rn.f32x2 %0, %1, %2, %0;" : "+l"(acc[0]) : "l"(xp), "l"(wab.x));
                asm("fma.rn.f32x2 %0, %1, %2, %0;" : "+l"(acc[1]) : "l"(xp), "l"(wab.y));
                asm("fma.rn.f32x2 %0, %1, %2, %0;" : "+l"(acc[2]) : "l"(xp), "l"(wcd.x));
                asm("fma.rn.f32x2 %0, %1, %2, %0;" : "+l"(acc[3]) : "l"(xp), "l"(wcd.y));
                asm("fma.rn.f32x2 %0, %1, %2, %0;" : "+l"(acc[4]) : "l"(xp), "l"(we));
            }
        }
    };

#pragma unroll 1
    for (int tile = 0; tile < NTILES; tile++) {
        int buf = tile & 1;
        if (tile + 1 < NTILES) {
            stage_x(tile + 1, buf ^ 1);
            asm volatile("cp.async.commit_group;");
            asm volatile("cp.async.wait_group 1;");
        } else {
            asm volatile("cp.async.wait_group 0;");
        }
        __syncthreads();
        compute(buf, tile);
        __syncthreads();   // protects buf before restage at tile+2
    }

    // Cross-warp reduction (deterministic, fixed order) -> partials.
    float* red = xs0;   // reuse x smem: 256*10 floats
#pragma unroll
    for (int q = 0; q < 5; q++) {
        float lo, hi;
        asm("mov.b64 {%0,%1}, %2;" : "=f"(lo), "=f"(hi) : "l"(acc[q]));
        red[t * NCLS_ + 2 * q]     = lo;
        red[t * NCLS_ + 2 * q + 1] = hi;
    }
    __syncthreads();
    for (int i = t; i < ROWS_ * NCLS_; i += 256) {   // 320 > 256: strided
        int row = i / NCLS_;
        int k   = i - row * NCLS_;
        float sum = 0.f;
#pragma unroll
        for (int w = 0; w < 8; w++) sum += red[(w * 32 + row) * NCLS_ + k];
        g_partial[((size_t)s * B_ + g * ROWS_ + row) * NCLS_ + k] = sum;
    }
}

// ---------------------------------------------------------------------------
// Finalize: out[n,k] = beff[k] + sum_s partial[s,n,k]
// 2 outputs/thread (float2), slice loop fully unrolled -> MLP ~32.
// o even => k even => (k, k+1) never crosses a row-of-10 boundary.
// ---------------------------------------------------------------------------
__global__ void __launch_bounds__(128)
finalize_k(float* __restrict__ out) {
    int tid = blockIdx.x * blockDim.x + threadIdx.x;  // 0..2559
    if (tid >= B_ * NCLS_ / 2) return;
    int o = tid * 2;
    int k = o % NCLS_;
    float2 v[SLICES];
#pragma unroll
    for (int s = 0; s < SLICES; s++)
        v[s] = *(const float2*)&g_partial[s * (B_ * NCLS_) + o];
    float s0 = g_beff[k], s1 = g_beff[k + 1];
#pragma unroll
    for (int s = 0; s < SLICES; s++) { s0 += v[s].x; s1 += v[s].y; }
    *(float2*)&out[o] = make_float2(s0, s1);
}

// ---------------------------------------------------------------------------
extern "C" void kernel_launch(void* const* d_in, const int* in_sizes, int n_in,
                              void* d_out, int out_size) {
    const float* x     = (const float*)d_in[0];   // [512, 65536]
    const float* W_fgl = (const float*)d_in[1];   // [4, 512]
    const float* b_fgl = (const float*)d_in[2];   // [4, 512]
    const float* W_fc  = (const float*)d_in[3];   // [2048, 10]
    const float* b_fc  = (const float*)d_in[4];   // [10]
    const int*   seg   = (const int*)d_in[5];     // [65536]
    float* out = (float*)d_out;                   // [512, 10]

    // Opt in to >48KB dynamic smem (host attribute set; idempotent, no alloc,
    // not a stream op -> graph-capture safe).
    cudaFuncSetAttribute(fused_main_k,
                         cudaFuncAttributeMaxDynamicSharedMemorySize, SMEM_TOTAL);

    prep_k<<<17, 320>>>(W_fgl, b_fgl, W_fc, b_fc);
    fused_main_k<<<dim3(SLICES, RGROUPS), 256, SMEM_TOTAL>>>(x, seg);
    finalize_k<<<(B_ * NCLS_ / 2 + 127) / 128, 128>>>(out);
    (void)in_sizes; (void)n_in; (void)out_size;
}

// round 7
// speedup vs baseline: 1.2010x; 1.0406x over previous
#include <cuda_runtime.h>
#include <cstdint>

// Problem constants
#define B_       512
#define P_       65536
#define NOUT_    512
#define COUT_    4
#define NCLS_    10

// Tiling
#define SLICES   32
#define SLICE_P  (P_ / SLICES)       // 2048
#define TILE_P   128
#define NTILES   (SLICE_P / TILE_P)  // 16
#define ROWS_    32
#define RGROUPS  (B_ / ROWS_)        // 16
#define XSTRIDE  132                 // smem row stride in floats (528B, conflict-free LDS.128)
#define WPAD     12                  // Weff row padded to 12 floats (48B)
#define DEPTH    4                   // cp.async pipeline stages

// Dynamic smem layout (bytes): [xs(4 bufs) | wsm | segs]
#define XBUF_FLOATS (ROWS_ * XSTRIDE)                 // 4224
#define XS_BYTES    (DEPTH * XBUF_FLOATS * 4)         // 67584
#define WSM_BYTES   (NOUT_ * WPAD * 4)                // 24576
#define SEG_BYTES   (SLICE_P * 4)                     // 8192
#define SMEM_TOTAL  (XS_BYTES + WSM_BYTES + SEG_BYTES)  // 100352

// Scratch (allocation-free: __device__ globals)
__device__ float g_Weff[NOUT_ * WPAD];            // padded [512][12]
__device__ float g_beff[NCLS_];
__device__ float g_partial[SLICES * B_ * NCLS_];  // per-slice partial sums

__device__ __forceinline__ uint32_t smem_u32(const void* p) {
    return (uint32_t)__cvta_generic_to_shared(p);
}
__device__ __forceinline__ void cp16(void* smem, const void* gmem) {
    uint32_t a = smem_u32(smem);
    asm volatile("cp.async.cg.shared.global [%0], [%1], 16;" :: "r"(a), "l"(gmem));
}
__device__ __forceinline__ unsigned long long packf2(float v) {
    unsigned long long r;
    asm("mov.b64 %0, {%1, %1};" : "=l"(r) : "f"(v));
    return r;
}

// ---------------------------------------------------------------------------
// Prep: Weff[j][k] = sum_c W_fgl[c,j] * W_fc[c*NOUT+j, k]   (padded rows)
//       beff[k]    = b_fc[k] + sum_{c,j} b_fgl[c,j] * W_fc[c*NOUT+j, k]
// R6 fix: beff path was a 256-long serial FADD chain by 10 threads (8.9us,
// latency-bound). Now: fully-unrolled MLP gather + tree reduction.
// ---------------------------------------------------------------------------
__global__ void prep_k(const float* __restrict__ W_fgl,
                       const float* __restrict__ b_fgl,
                       const float* __restrict__ W_fc,
                       const float* __restrict__ b_fc) {
    if (blockIdx.x < 16) {
        int t = threadIdx.x;                  // 0..319
        int j = blockIdx.x * 32 + t / NCLS_;
        int k = t % NCLS_;
        float s = 0.f;
#pragma unroll
        for (int c = 0; c < COUT_; c++) {
            int r = c * NOUT_ + j;
            s += W_fgl[r] * W_fc[r * NCLS_ + k];
        }
        g_Weff[j * WPAD + k] = s;
        if (k < 2) g_Weff[j * WPAD + 10 + k] = 0.f;   // pad (never read, keep defined)
    } else {
        __shared__ float red[256][NCLS_];
        int t = threadIdx.x;
        if (t < 256) {
            float loc[NCLS_];
#pragma unroll
            for (int k = 0; k < NCLS_; k++) loc[k] = 0.f;
#pragma unroll
            for (int it = 0; it < COUT_ * NOUT_ / 256; it++) {   // 8, unrolled -> MLP
                int r = t + it * 256;
                float bb = b_fgl[r];
#pragma unroll
                for (int k = 0; k < NCLS_; k++) loc[k] += bb * W_fc[r * NCLS_ + k];
            }
#pragma unroll
            for (int k = 0; k < NCLS_; k++) red[t][k] = loc[k];
        }
        __syncthreads();
        // tree: 256 -> 32 rows (fixed order, deterministic)
#pragma unroll
        for (int off = 128; off >= 32; off >>= 1) {
            if (t < off) {
#pragma unroll
                for (int k = 0; k < NCLS_; k++) red[t][k] += red[t + off][k];
            }
            __syncthreads();
        }
        if (t < NCLS_) {
            float a0 = 0.f, a1 = 0.f, a2 = 0.f, a3 = 0.f;   // 4 chains
#pragma unroll
            for (int i = 0; i < 32; i += 4) {
                a0 += red[i][t]; a1 += red[i + 1][t];
                a2 += red[i + 2][t]; a3 += red[i + 3][t];
            }
            g_beff[t] = b_fc[t] + ((a0 + a1) + (a2 + a3));
        }
    }
}

// ---------------------------------------------------------------------------
// Main: partial[s, n, k] = sum_{p in slice s} x[n,p] * Weff[seg[p]][k]
// Block (s, g): 32 rows (lane == row), 2048-p slice.
// 4-stage cp.async pipeline, ONE __syncthreads per tile:
//   prologue stages tiles 0..2; iter i: wait_group 2 (tile i arrived; one
//   group committed per iter, empty groups near the end keep the count
//   uniform) -> barrier -> stage(i+3) into buf (i-1)%4 (safe: every warp
//   passed barrier(i) only after compute(i-1)) -> commit -> compute(i).
// Weff (24KB) + seg slice (8KB) resident in dynamic smem; weight lookup is a
// uniform per-warp address -> broadcast LDS.
// ---------------------------------------------------------------------------
__global__ void __launch_bounds__(256, 2)
fused_main_k(const float* __restrict__ x, const int* __restrict__ seg) {
    extern __shared__ __align__(16) char dynsmem[];
    float* xs0  = (float*)dynsmem;                         // [DEPTH][XBUF_FLOATS]
    float* wsm  = (float*)(dynsmem + XS_BYTES);            // [NOUT_*WPAD]
    int*   segs = (int*)(dynsmem + XS_BYTES + WSM_BYTES);  // [SLICE_P]

    const int t    = threadIdx.x;
    const int warp = t >> 5;
    const int lane = t & 31;
    const int s    = blockIdx.x;
    const int g    = blockIdx.y;

    const float* xbase = x + (size_t)(g * ROWS_) * P_ + (size_t)s * SLICE_P;

    auto stage_x = [&](int tile, int buf) {
        const int pOff = tile * TILE_P;
        float* xsb = xs0 + buf * XBUF_FLOATS;
#pragma unroll
        for (int r = 0; r < 4; r++) {
            int f   = r * 256 + t;
            int row = f >> 5;            // 32 float4 per row
            int c4  = (f & 31) << 2;
            cp16(&xsb[row * XSTRIDE + c4], xbase + (size_t)row * P_ + pOff + c4);
        }
    };

    // Prologue: group0 = {Weff, segs, tile0}; group1 = tile1; group2 = tile2.
    {
        const float4* wsrc = (const float4*)g_Weff;          // 1536 float4
#pragma unroll
        for (int r = 0; r < 6; r++)
            cp16(&((float4*)wsm)[r * 256 + t], wsrc + r * 256 + t);
        const float4* ssrc = (const float4*)(seg + s * SLICE_P);  // 512 float4
#pragma unroll
        for (int r = 0; r < 2; r++)
            cp16(&((float4*)segs)[r * 256 + t], ssrc + r * 256 + t);
    }
    stage_x(0, 0);
    asm volatile("cp.async.commit_group;");
    stage_x(1, 1);
    asm volatile("cp.async.commit_group;");
    stage_x(2, 2);
    asm volatile("cp.async.commit_group;");

    unsigned long long acc[5];   // f32x2 per class pair
#pragma unroll
    for (int q = 0; q < 5; q++) acc[q] = 0ull;

    auto compute = [&](int buf, int tile) {
        const float4* xrow =
            (const float4*)&xs0[buf * XBUF_FLOATS + lane * XSTRIDE + warp * 16];
        const int4* sp = (const int4*)&segs[tile * TILE_P + warp * 16];
#pragma unroll
        for (int step = 0; step < 4; step++) {
            float4 x4  = xrow[step];          // 4 pixels of this row (LDS.128)
            int4   sid = sp[step];            // 4 seg ids (uniform -> broadcast)
#pragma unroll
            for (int j = 0; j < 4; j++) {
                int   id = (j == 0) ? sid.x : (j == 1) ? sid.y : (j == 2) ? sid.z : sid.w;
                float xv = (j == 0) ? x4.x  : (j == 1) ? x4.y  : (j == 2) ? x4.z  : x4.w;
                const unsigned long long* wrow =
                    (const unsigned long long*)&wsm[id * WPAD];
                ulonglong2 wab = *(const ulonglong2*)(wrow);      // k0..3
                ulonglong2 wcd = *(const ulonglong2*)(wrow + 2);  // k4..7
                unsigned long long we = wrow[4];                   // k8..9
                unsigned long long xp = packf2(xv);
                asm("fma.rn.f32x2 %0, %1, %2, %0;" : "+l"(acc[0]) : "l"(xp), "l"(wab.x));
                asm("fma.rn.f32x2 %0, %1, %2, %0;" : "+l"(acc[1]) : "l"(xp), "l"(wab.y));
                asm("fma.rn.f32x2 %0, %1, %2, %0;" : "+l"(acc[2]) : "l"(xp), "l"(wcd.x));
                asm("fma.rn.f32x2 %0, %1, %2, %0;" : "+l"(acc[3]) : "l"(xp), "l"(wcd.y));
                asm("fma.rn.f32x2 %0, %1, %2, %0;" : "+l"(acc[4]) : "l"(xp), "l"(we));
            }
        }
    };

#pragma unroll 1
    for (int tile = 0; tile < NTILES; tile++) {
        asm volatile("cp.async.wait_group 2;");
        __syncthreads();
        if (tile + DEPTH - 1 < NTILES)
            stage_x(tile + DEPTH - 1, (tile + DEPTH - 1) & (DEPTH - 1));
        asm volatile("cp.async.commit_group;");   // possibly empty: keeps count uniform
        compute(tile & (DEPTH - 1), tile);
    }

    // Cross-warp reduction (deterministic, fixed order) -> partials.
    float* red = xs0;   // reuse buffer-0 region: 2560 floats
#pragma unroll
    for (int q = 0; q < 5; q++) {
        float lo, hi;
        asm("mov.b64 {%0,%1}, %2;" : "=f"(lo), "=f"(hi) : "l"(acc[q]));
        red[t * NCLS_ + 2 * q]     = lo;
        red[t * NCLS_ + 2 * q + 1] = hi;
    }
    __syncthreads();
    for (int i = t; i < ROWS_ * NCLS_; i += 256) {   // 320 > 256: strided
        int row = i / NCLS_;
        int k   = i - row * NCLS_;
        float sum = 0.f;
#pragma unroll
        for (int w = 0; w < 8; w++) sum += red[(w * 32 + row) * NCLS_ + k];
        g_partial[((size_t)s * B_ + g * ROWS_ + row) * NCLS_ + k] = sum;
    }
}

// ---------------------------------------------------------------------------
// Finalize: out[n,k] = beff[k] + sum_s partial[s,n,k]
// 2 outputs/thread (float2), slice loop fully unrolled -> MLP ~32.
// ---------------------------------------------------------------------------
__global__ void __launch_bounds__(128)
finalize_k(float* __restrict__ out) {
    int tid = blockIdx.x * blockDim.x + threadIdx.x;  // 0..2559
    if (tid >= B_ * NCLS_ / 2) return;
    int o = tid * 2;
    int k = o % NCLS_;
    float2 v[SLICES];
#pragma unroll
    for (int s = 0; s < SLICES; s++)
        v[s] = *(const float2*)&g_partial[s * (B_ * NCLS_) + o];
    float s0 = g_beff[k], s1 = g_beff[k + 1];
#pragma unroll
    for (int s = 0; s < SLICES; s++) { s0 += v[s].x; s1 += v[s].y; }
    *(float2*)&out[o] = make_float2(s0, s1);
}

// ---------------------------------------------------------------------------
extern "C" void kernel_launch(void* const* d_in, const int* in_sizes, int n_in,
                              void* d_out, int out_size) {
    const float* x     = (const float*)d_in[0];   // [512, 65536]
    const float* W_fgl = (const float*)d_in[1];   // [4, 512]
    const float* b_fgl = (const float*)d_in[2];   // [4, 512]
    const float* W_fc  = (const float*)d_in[3];   // [2048, 10]
    const float* b_fc  = (const float*)d_in[4];   // [10]
    const int*   seg   = (const int*)d_in[5];     // [65536]
    float* out = (float*)d_out;                   // [512, 10]

    cudaFuncSetAttribute(fused_main_k,
                         cudaFuncAttributeMaxDynamicSharedMemorySize, SMEM_TOTAL);

    prep_k<<<17, 320>>>(W_fgl, b_fgl, W_fc, b_fc);
    fused_main_k<<<dim3(SLICES, RGROUPS), 256, SMEM_TOTAL>>>(x, seg);
    finalize_k<<<(B_ * NCLS_ / 2 + 127) / 128, 128>>>(out);
    (void)in_sizes; (void)n_in; (void)out_size;
}